// round 1
// baseline (speedup 1.0000x reference)
#include <cuda_runtime.h>
#include <math.h>

// ---------------------------------------------------------------------------
// SpecDecoder: 127-step LSTM + 3-layer MLP decoder, persistent-kernel fp32.
// B=1024, H=512, E=256, L=128.
// ---------------------------------------------------------------------------

#define BATCH 1024
#define HID   512
#define EMB   256
#define SEQL  128
#define STEPS (SEQL - 1)
#define G4H   2048            // 4*HID
#define KGATE 768             // EMB + HID
#define NBLK  128
#define NTHR  256

// ---------------- device scratch (static allocation only) ------------------
__device__ float g_Wp[G4H * KGATE];    // gate-interleaved weights: row n'=4j+g
__device__ float g_bp[G4H];            // permuted combined bias
__device__ float g_h[2][BATCH * HID];  // double-buffered hidden state
__device__ float g_c[BATCH * HID];     // cell state (in-place update)
__device__ float g_z1[BATCH * 128];
__device__ float g_z2[BATCH * 128];
__device__ unsigned g_bar;             // grid barrier counter (monotonic)

// ---------------------------------------------------------------------------
// Grid-wide barrier (all NBLK CTAs co-resident). Release/acquire via
// __threadfence (fence.gpu -> CCTL.IVALL flushes stale L1 on sm_10x).
// ---------------------------------------------------------------------------
__device__ __forceinline__ void grid_sync() {
    __syncthreads();
    if (threadIdx.x == 0) {
        __threadfence();                       // release prior writes
        unsigned old = atomicAdd(&g_bar, 1u);
        unsigned target = (old / NBLK + 1u) * NBLK;
        while (*((volatile unsigned*)&g_bar) < target) { }
        __threadfence();                       // acquire (invalidate L1)
    }
    __syncthreads();
}

// ---------------------------------------------------------------------------
// Init kernel: start token, h0/c0, barrier reset, gate-interleaved weights.
// ---------------------------------------------------------------------------
__global__ void init_kernel(const float* __restrict__ hidden,
                            const float* __restrict__ W_ih,
                            const float* __restrict__ W_hh,
                            const float* __restrict__ b_ih,
                            const float* __restrict__ b_hh,
                            float* __restrict__ out) {
    int idx = blockIdx.x * blockDim.x + threadIdx.x;
    int stride = gridDim.x * blockDim.x;
    if (idx == 0) g_bar = 0u;

    for (int i = idx; i < BATCH * HID; i += stride) {
        g_h[0][i] = hidden[i];
        g_c[i] = 0.f;
    }
    // out[:, 0, :] = one-hot at index 0
    for (int i = idx; i < BATCH * EMB; i += stride) {
        int b = i / EMB, e = i % EMB;
        out[(size_t)b * (SEQL * EMB) + e] = (e == 0) ? 1.f : 0.f;
    }
    // permuted weights: n' = 4*j + g  <->  original row n = g*HID + j
    for (int i = idx; i < G4H * KGATE; i += stride) {
        int np = i / KGATE, k = i % KGATE;
        int g = np & 3, j = np >> 2;
        int n = g * HID + j;
        g_Wp[i] = (k < EMB) ? W_ih[n * EMB + k] : W_hh[n * HID + (k - EMB)];
    }
    for (int i = idx; i < G4H; i += stride) {
        int g = i & 3, j = i >> 2;
        int n = g * HID + j;
        g_bp[i] = b_ih[n] + b_hh[n];
    }
}

// ---------------------------------------------------------------------------
// Phase A: gates GEMM (1024 x 2048, K=768) with fused LSTM update epilogue.
// Tile 128x128, 256 threads, 8x8 micro-tile arranged so each thread owns
// complete (i,f,g,o) quadruples in the gate-interleaved layout.
// ---------------------------------------------------------------------------
__device__ void phase_gates(const float* __restrict__ pts, int t, int cur,
                            float* smem) {
    const int tile = blockIdx.x;               // exactly 128 tiles
    const int mb = (tile >> 4) * 128;          // batch-row base (8 tiles)
    const int nb = (tile & 15) * 128;          // permuted gate-col base (16)
    const int tid = threadIdx.x;
    const int tx = tid & 15, ty = tid >> 4;

    float* sA = smem;                          // [16][132]
    float* sB = smem + 16 * 132;               // [16][132]

    float acc[8][8];
#pragma unroll
    for (int r = 0; r < 8; r++)
#pragma unroll
        for (int c = 0; c < 8; c++) acc[r][c] = 0.f;

    const float* hcur = g_h[cur];
    const int krow = tid & 15;                 // k lane within chunk
    const int mrow = tid >> 4;                 // base row for loads

    for (int kc = 0; kc < KGATE; kc += 16) {
        int k = kc + krow;
        if (k < EMB) {
            const float* xp = pts + (size_t)t * EMB + k;
#pragma unroll
            for (int p = 0; p < 8; p++) {
                int m = mrow + p * 16;
                sA[krow * 132 + m] = xp[(size_t)(mb + m) * (SEQL * EMB)];
            }
        } else {
            const float* hp = hcur + (k - EMB);
#pragma unroll
            for (int p = 0; p < 8; p++) {
                int m = mrow + p * 16;
                sA[krow * 132 + m] = hp[(mb + m) * HID];
            }
        }
        const float* wp = g_Wp + (size_t)nb * KGATE + k;
#pragma unroll
        for (int p = 0; p < 8; p++) {
            int n = mrow + p * 16;
            sB[krow * 132 + n] = wp[n * KGATE];
        }
        __syncthreads();
#pragma unroll
        for (int kk = 0; kk < 16; kk++) {
            float4 a0 = *(const float4*)&sA[kk * 132 + ty * 4];
            float4 a1 = *(const float4*)&sA[kk * 132 + 64 + ty * 4];
            float4 b0 = *(const float4*)&sB[kk * 132 + tx * 4];
            float4 b1 = *(const float4*)&sB[kk * 132 + 64 + tx * 4];
            float a[8] = {a0.x, a0.y, a0.z, a0.w, a1.x, a1.y, a1.z, a1.w};
            float bv[8] = {b0.x, b0.y, b0.z, b0.w, b1.x, b1.y, b1.z, b1.w};
#pragma unroll
            for (int r = 0; r < 8; r++)
#pragma unroll
                for (int c = 0; c < 8; c++)
                    acc[r][c] += a[r] * bv[c];
        }
        __syncthreads();
    }

    // Fused LSTM update epilogue: each thread holds 8 rows x 2 full units.
    float* hn = g_h[cur ^ 1];
#pragma unroll
    for (int r = 0; r < 8; r++) {
        int m = mb + ((r < 4) ? (ty * 4 + r) : (64 + ty * 4 + (r - 4)));
#pragma unroll
        for (int ug = 0; ug < 2; ug++) {
            int ncol = nb + ug * 64 + tx * 4;  // n' of gate i for this unit
            int j = ncol >> 2;                 // unit index within HID
            float gi = acc[r][ug * 4 + 0] + g_bp[ncol + 0];
            float gf = acc[r][ug * 4 + 1] + g_bp[ncol + 1];
            float gg = acc[r][ug * 4 + 2] + g_bp[ncol + 2];
            float go = acc[r][ug * 4 + 3] + g_bp[ncol + 3];
            float ii = 1.f / (1.f + __expf(-gi));
            float ff = 1.f / (1.f + __expf(-gf));
            float tg = tanhf(gg);
            float oo = 1.f / (1.f + __expf(-go));
            float cn = ff * g_c[m * HID + j] + ii * tg;
            g_c[m * HID + j] = cn;
            hn[m * HID + j] = oo * tanhf(cn);
        }
    }
}

// ---------------------------------------------------------------------------
// Small GEMM for the MLP layers: C[m][n] = act(A[m]·W[n] + bias[n]).
// 32x32 tiles, 256 threads, 2x2 micro-tile. Tiles strided over NBLK CTAs.
// ---------------------------------------------------------------------------
template <int N, int K, bool RELU>
__device__ void mlp_gemm(const float* __restrict__ Ain, int ldA,
                         const float* __restrict__ W,
                         const float* __restrict__ bias,
                         float* __restrict__ Cout, int ldC, float* smem) {
    float* sA = smem;              // [16][33]
    float* sB = smem + 16 * 33;    // [16][33]
    const int tid = threadIdx.x;
    const int tx = tid & 15, ty = tid >> 4;
    const int ncolt = N / 32;
    const int ntiles = (BATCH / 32) * ncolt;

    for (int tile = blockIdx.x; tile < ntiles; tile += NBLK) {
        int mb = (tile / ncolt) * 32;
        int nb = (tile % ncolt) * 32;
        float acc00 = 0.f, acc01 = 0.f, acc10 = 0.f, acc11 = 0.f;
        for (int kc = 0; kc < K; kc += 16) {
            int k = tid & 15, r = tid >> 4;    // r: 0..15
            sA[k * 33 + r]      = Ain[(mb + r) * ldA + kc + k];
            sA[k * 33 + r + 16] = Ain[(mb + r + 16) * ldA + kc + k];
            sB[k * 33 + r]      = W[(nb + r) * K + kc + k];
            sB[k * 33 + r + 16] = W[(nb + r + 16) * K + kc + k];
            __syncthreads();
#pragma unroll
            for (int kk = 0; kk < 16; kk++) {
                float a0 = sA[kk * 33 + ty * 2];
                float a1 = sA[kk * 33 + ty * 2 + 1];
                float b0 = sB[kk * 33 + tx * 2];
                float b1 = sB[kk * 33 + tx * 2 + 1];
                acc00 += a0 * b0; acc01 += a0 * b1;
                acc10 += a1 * b0; acc11 += a1 * b1;
            }
            __syncthreads();
        }
        {
            int m0 = mb + ty * 2, n0 = nb + tx * 2;
            float v00 = acc00 + bias[n0];
            float v01 = acc01 + bias[n0 + 1];
            float v10 = acc10 + bias[n0];
            float v11 = acc11 + bias[n0 + 1];
            if (RELU) {
                v00 = fmaxf(v00, 0.f); v01 = fmaxf(v01, 0.f);
                v10 = fmaxf(v10, 0.f); v11 = fmaxf(v11, 0.f);
            }
            Cout[(size_t)m0 * ldC + n0]           = v00;
            Cout[(size_t)m0 * ldC + n0 + 1]       = v01;
            Cout[(size_t)(m0 + 1) * ldC + n0]     = v10;
            Cout[(size_t)(m0 + 1) * ldC + n0 + 1] = v11;
        }
    }
}

// ---------------------------------------------------------------------------
// Persistent kernel: 127 steps, 3 grid syncs per step.
// ---------------------------------------------------------------------------
__global__ void __launch_bounds__(NTHR, 1)
lstm_kernel(const float* __restrict__ pts,
            const float* __restrict__ W1, const float* __restrict__ b1,
            const float* __restrict__ W2, const float* __restrict__ b2,
            const float* __restrict__ W3, const float* __restrict__ b3,
            float* __restrict__ out) {
    __shared__ float smem[2 * 16 * 132];
    int cur = 0;
    for (int t = 0; t < STEPS; t++) {
        // gates GEMM + fused LSTM update: h[cur] -> h[nxt], c in place
        phase_gates(pts, t, cur, smem);
        grid_sync();
        int nxt = cur ^ 1;
        // z1 = relu(h @ W1^T + b1)
        mlp_gemm<128, HID, true>(g_h[nxt], HID, W1, b1, g_z1, 128, smem);
        grid_sync();
        // z2 = relu(z1 @ W2^T + b2)
        mlp_gemm<128, 128, true>(g_z1, 128, W2, b2, g_z2, 128, smem);
        grid_sync();
        // tok = z2 @ W3^T + b3 -> out[:, t+1, :]
        mlp_gemm<EMB, 128, false>(g_z2, 128, W3, b3,
                                  out + (size_t)(t + 1) * EMB, SEQL * EMB, smem);
        // no barrier needed before next phase A (see ordering argument):
        // every CTA finishes its own phase D before arriving at the next
        // step's first barrier, and buffers touched here are only re-written
        // after that barrier.
        cur = nxt;
    }
}

// ---------------------------------------------------------------------------
extern "C" void kernel_launch(void* const* d_in, const int* in_sizes, int n_in,
                              void* d_out, int out_size) {
    (void)in_sizes; (void)n_in; (void)out_size;
    const float* hidden = (const float*)d_in[0];
    const float* pts    = (const float*)d_in[1];
    const float* W_ih   = (const float*)d_in[2];
    const float* W_hh   = (const float*)d_in[3];
    const float* b_ih   = (const float*)d_in[4];
    const float* b_hh   = (const float*)d_in[5];
    const float* W1     = (const float*)d_in[6];
    const float* b1     = (const float*)d_in[7];
    const float* W2     = (const float*)d_in[8];
    const float* b2     = (const float*)d_in[9];
    const float* W3     = (const float*)d_in[10];
    const float* b3     = (const float*)d_in[11];
    float* out = (float*)d_out;

    init_kernel<<<256, 256>>>(hidden, W_ih, W_hh, b_ih, b_hh, out);
    lstm_kernel<<<NBLK, NTHR>>>(pts, W1, b1, W2, b2, W3, b3, out);
}

// round 2
// speedup vs baseline: 1.0143x; 1.0143x over previous
#include <cuda_runtime.h>
#include <math.h>

// ---------------------------------------------------------------------------
// SpecDecoder: 127-step LSTM + 3-layer MLP decoder, persistent-kernel fp32.
// B=1024, H=512, E=256, L=128.
// ---------------------------------------------------------------------------

#define BATCH 1024
#define HID   512
#define EMB   256
#define SEQL  128
#define STEPS (SEQL - 1)
#define G4H   2048            // 4*HID
#define KGATE 768             // EMB + HID
#define NBLK  128
#define NTHR  256

// ---------------- device scratch (static allocation only) ------------------
__device__ float g_Wp[G4H * KGATE];    // gate-interleaved weights: row n'=4j+g
__device__ float g_bp[G4H];            // permuted combined bias
__device__ float g_h[2][BATCH * HID];  // double-buffered hidden state
__device__ float g_c[BATCH * HID];     // cell state (in-place update)
__device__ float g_z1[BATCH * 128];
__device__ float g_z2[BATCH * 128];
__device__ unsigned g_bar;             // grid barrier counter (monotonic)

// ---------------------------------------------------------------------------
// Grid-wide barrier (all NBLK CTAs co-resident). Release/acquire via
// __threadfence (fence.gpu -> CCTL.IVALL flushes stale L1 on sm_10x).
// ---------------------------------------------------------------------------
__device__ __forceinline__ void grid_sync() {
    __syncthreads();
    if (threadIdx.x == 0) {
        __threadfence();                       // release prior writes
        unsigned old = atomicAdd(&g_bar, 1u);
        unsigned target = (old / NBLK + 1u) * NBLK;
        while (*((volatile unsigned*)&g_bar) < target) { }
        __threadfence();                       // acquire (invalidate L1)
    }
    __syncthreads();
}

// ---------------------------------------------------------------------------
// Init kernel: start token, h0/c0, barrier reset, gate-interleaved weights.
// ---------------------------------------------------------------------------
__global__ void init_kernel(const float* __restrict__ hidden,
                            const float* __restrict__ W_ih,
                            const float* __restrict__ W_hh,
                            const float* __restrict__ b_ih,
                            const float* __restrict__ b_hh,
                            float* __restrict__ out) {
    int idx = blockIdx.x * blockDim.x + threadIdx.x;
    int stride = gridDim.x * blockDim.x;
    if (idx == 0) g_bar = 0u;

    for (int i = idx; i < BATCH * HID; i += stride) {
        g_h[0][i] = hidden[i];
        g_c[i] = 0.f;
    }
    // out[:, 0, :] = one-hot at index 0
    for (int i = idx; i < BATCH * EMB; i += stride) {
        int b = i / EMB, e = i % EMB;
        out[(size_t)b * (SEQL * EMB) + e] = (e == 0) ? 1.f : 0.f;
    }
    // permuted weights: n' = 4*j + g  <->  original row n = g*HID + j
    for (int i = idx; i < G4H * KGATE; i += stride) {
        int np = i / KGATE, k = i % KGATE;
        int g = np & 3, j = np >> 2;
        int n = g * HID + j;
        g_Wp[i] = (k < EMB) ? W_ih[n * EMB + k] : W_hh[n * HID + (k - EMB)];
    }
    for (int i = idx; i < G4H; i += stride) {
        int g = i & 3, j = i >> 2;
        int n = g * HID + j;
        g_bp[i] = b_ih[n] + b_hh[n];
    }
}

// ---------------------------------------------------------------------------
// Phase A: gates GEMM (1024 x 2048, K=768) with fused LSTM update epilogue.
// Tile 128x128, 256 threads, 8x8 micro-tile arranged so each thread owns
// complete (i,f,g,o) quadruples in the gate-interleaved layout.
// ---------------------------------------------------------------------------
__device__ void phase_gates(const float* __restrict__ pts, int t, int cur,
                            float* smem) {
    const int tile = blockIdx.x;               // exactly 128 tiles
    const int mb = (tile >> 4) * 128;          // batch-row base (8 tiles)
    const int nb = (tile & 15) * 128;          // permuted gate-col base (16)
    const int tid = threadIdx.x;
    const int tx = tid & 15, ty = tid >> 4;

    float* sA = smem;                          // [16][132]
    float* sB = smem + 16 * 132;               // [16][132]

    float acc[8][8];
#pragma unroll
    for (int r = 0; r < 8; r++)
#pragma unroll
        for (int c = 0; c < 8; c++) acc[r][c] = 0.f;

    const float* hcur = g_h[cur];
    const int krow = tid & 15;                 // k lane within chunk
    const int mrow = tid >> 4;                 // base row for loads

    for (int kc = 0; kc < KGATE; kc += 16) {
        int k = kc + krow;
        if (k < EMB) {
            const float* xp = pts + (size_t)t * EMB + k;
#pragma unroll
            for (int p = 0; p < 8; p++) {
                int m = mrow + p * 16;
                sA[krow * 132 + m] = xp[(size_t)(mb + m) * (SEQL * EMB)];
            }
        } else {
            const float* hp = hcur + (k - EMB);
#pragma unroll
            for (int p = 0; p < 8; p++) {
                int m = mrow + p * 16;
                sA[krow * 132 + m] = hp[(mb + m) * HID];
            }
        }
        const float* wp = g_Wp + (size_t)nb * KGATE + k;
#pragma unroll
        for (int p = 0; p < 8; p++) {
            int n = mrow + p * 16;
            sB[krow * 132 + n] = wp[n * KGATE];
        }
        __syncthreads();
#pragma unroll
        for (int kk = 0; kk < 16; kk++) {
            float4 a0 = *(const float4*)&sA[kk * 132 + ty * 4];
            float4 a1 = *(const float4*)&sA[kk * 132 + 64 + ty * 4];
            float4 b0 = *(const float4*)&sB[kk * 132 + tx * 4];
            float4 b1 = *(const float4*)&sB[kk * 132 + 64 + tx * 4];
            float a[8] = {a0.x, a0.y, a0.z, a0.w, a1.x, a1.y, a1.z, a1.w};
            float bv[8] = {b0.x, b0.y, b0.z, b0.w, b1.x, b1.y, b1.z, b1.w};
#pragma unroll
            for (int r = 0; r < 8; r++)
#pragma unroll
                for (int c = 0; c < 8; c++)
                    acc[r][c] += a[r] * bv[c];
        }
        __syncthreads();
    }

    // Fused LSTM update epilogue: each thread holds 8 rows x 2 full units.
    float* hn = g_h[cur ^ 1];
#pragma unroll
    for (int r = 0; r < 8; r++) {
        int m = mb + ((r < 4) ? (ty * 4 + r) : (64 + ty * 4 + (r - 4)));
#pragma unroll
        for (int ug = 0; ug < 2; ug++) {
            int ncol = nb + ug * 64 + tx * 4;  // n' of gate i for this unit
            int j = ncol >> 2;                 // unit index within HID
            float gi = acc[r][ug * 4 + 0] + g_bp[ncol + 0];
            float gf = acc[r][ug * 4 + 1] + g_bp[ncol + 1];
            float gg = acc[r][ug * 4 + 2] + g_bp[ncol + 2];
            float go = acc[r][ug * 4 + 3] + g_bp[ncol + 3];
            float ii = 1.f / (1.f + __expf(-gi));
            float ff = 1.f / (1.f + __expf(-gf));
            float tg = tanhf(gg);
            float oo = 1.f / (1.f + __expf(-go));
            float cn = ff * g_c[m * HID + j] + ii * tg;
            g_c[m * HID + j] = cn;
            hn[m * HID + j] = oo * tanhf(cn);
        }
    }
}

// ---------------------------------------------------------------------------
// Small GEMM for the MLP layers: C[m][n] = act(A[m]·W[n] + bias[n]).
// 32x32 tiles, 256 threads, 2x2 micro-tile. Tiles strided over NBLK CTAs.
// ---------------------------------------------------------------------------
template <int N, int K, bool RELU>
__device__ void mlp_gemm(const float* __restrict__ Ain, int ldA,
                         const float* __restrict__ W,
                         const float* __restrict__ bias,
                         float* __restrict__ Cout, int ldC, float* smem) {
    float* sA = smem;              // [16][33]
    float* sB = smem + 16 * 33;    // [16][33]
    const int tid = threadIdx.x;
    const int tx = tid & 15, ty = tid >> 4;
    const int ncolt = N / 32;
    const int ntiles = (BATCH / 32) * ncolt;

    for (int tile = blockIdx.x; tile < ntiles; tile += NBLK) {
        int mb = (tile / ncolt) * 32;
        int nb = (tile % ncolt) * 32;
        float acc00 = 0.f, acc01 = 0.f, acc10 = 0.f, acc11 = 0.f;
        for (int kc = 0; kc < K; kc += 16) {
            int k = tid & 15, r = tid >> 4;    // r: 0..15
            sA[k * 33 + r]      = Ain[(mb + r) * ldA + kc + k];
            sA[k * 33 + r + 16] = Ain[(mb + r + 16) * ldA + kc + k];
            sB[k * 33 + r]      = W[(nb + r) * K + kc + k];
            sB[k * 33 + r + 16] = W[(nb + r + 16) * K + kc + k];
            __syncthreads();
#pragma unroll
            for (int kk = 0; kk < 16; kk++) {
                float a0 = sA[kk * 33 + ty * 2];
                float a1 = sA[kk * 33 + ty * 2 + 1];
                float b0 = sB[kk * 33 + tx * 2];
                float b1 = sB[kk * 33 + tx * 2 + 1];
                acc00 += a0 * b0; acc01 += a0 * b1;
                acc10 += a1 * b0; acc11 += a1 * b1;
            }
            __syncthreads();
        }
        {
            int m0 = mb + ty * 2, n0 = nb + tx * 2;
            float v00 = acc00 + bias[n0];
            float v01 = acc01 + bias[n0 + 1];
            float v10 = acc10 + bias[n0];
            float v11 = acc11 + bias[n0 + 1];
            if (RELU) {
                v00 = fmaxf(v00, 0.f); v01 = fmaxf(v01, 0.f);
                v10 = fmaxf(v10, 0.f); v11 = fmaxf(v11, 0.f);
            }
            Cout[(size_t)m0 * ldC + n0]           = v00;
            Cout[(size_t)m0 * ldC + n0 + 1]       = v01;
            Cout[(size_t)(m0 + 1) * ldC + n0]     = v10;
            Cout[(size_t)(m0 + 1) * ldC + n0 + 1] = v11;
        }
    }
}

// ---------------------------------------------------------------------------
// Persistent kernel: 127 steps, 3 grid syncs per step.
// ---------------------------------------------------------------------------
__global__ void __launch_bounds__(NTHR, 1)
lstm_kernel(const float* __restrict__ pts,
            const float* __restrict__ W1, const float* __restrict__ b1,
            const float* __restrict__ W2, const float* __restrict__ b2,
            const float* __restrict__ W3, const float* __restrict__ b3,
            float* __restrict__ out) {
    __shared__ float smem[2 * 16 * 132];
    int cur = 0;
    for (int t = 0; t < STEPS; t++) {
        // gates GEMM + fused LSTM update: h[cur] -> h[nxt], c in place
        phase_gates(pts, t, cur, smem);
        grid_sync();
        int nxt = cur ^ 1;
        // z1 = relu(h @ W1^T + b1)
        mlp_gemm<128, HID, true>(g_h[nxt], HID, W1, b1, g_z1, 128, smem);
        grid_sync();
        // z2 = relu(z1 @ W2^T + b2)
        mlp_gemm<128, 128, true>(g_z1, 128, W2, b2, g_z2, 128, smem);
        grid_sync();
        // tok = z2 @ W3^T + b3 -> out[:, t+1, :]
        mlp_gemm<EMB, 128, false>(g_z2, 128, W3, b3,
                                  out + (size_t)(t + 1) * EMB, SEQL * EMB, smem);
        // no barrier needed before next phase A (see ordering argument):
        // every CTA finishes its own phase D before arriving at the next
        // step's first barrier, and buffers touched here are only re-written
        // after that barrier.
        cur = nxt;
    }
}

// ---------------------------------------------------------------------------
extern "C" void kernel_launch(void* const* d_in, const int* in_sizes, int n_in,
                              void* d_out, int out_size) {
    (void)in_sizes; (void)n_in; (void)out_size;
    const float* hidden = (const float*)d_in[0];
    const float* pts    = (const float*)d_in[1];
    const float* W_ih   = (const float*)d_in[2];
    const float* W_hh   = (const float*)d_in[3];
    const float* b_ih   = (const float*)d_in[4];
    const float* b_hh   = (const float*)d_in[5];
    const float* W1     = (const float*)d_in[6];
    const float* b1     = (const float*)d_in[7];
    const float* W2     = (const float*)d_in[8];
    const float* b2     = (const float*)d_in[9];
    const float* W3     = (const float*)d_in[10];
    const float* b3     = (const float*)d_in[11];
    float* out = (float*)d_out;

    init_kernel<<<256, 256>>>(hidden, W_ih, W_hh, b_ih, b_hh, out);
    lstm_kernel<<<NBLK, NTHR>>>(pts, W1, b1, W2, b2, W3, b3, out);
}

// round 3
// speedup vs baseline: 1.7483x; 1.7236x over previous
#include <cuda_runtime.h>
#include <math.h>
#include <stdint.h>

// ---------------------------------------------------------------------------
// SpecDecoder: 127-step LSTM + 3-layer MLP decoder.
// Gates GEMM on tensor cores (mma.sync tf32) with fused LSTM epilogue.
// B=1024, H=512, E=256, L=128.
// ---------------------------------------------------------------------------

#define BATCH 1024
#define HID   512
#define EMB   256
#define SEQL  128
#define STEPS (SEQL - 1)
#define G4H   2048            // 4*HID
#define KGATE 768             // EMB + HID
#define NBLK  128
#define NTHR  256
#define BK    16
#define NCHUNK (KGATE / BK)   // 48
#define SROW  20              // smem row stride (floats): conflict-free
#define SBUF  (128 * SROW)    // 2560 floats per buffer

// ---------------- device scratch (static allocation only) ------------------
__device__ float g_Wp[G4H * KGATE];    // permuted, tf32-rounded weights [n'][k]
__device__ float g_bc[G4H];            // combined bias, ORIGINAL order
__device__ float g_h[2][BATCH * HID];  // double-buffered hidden state
__device__ float g_c[BATCH * HID];     // cell state (in-place)
__device__ float g_z1[BATCH * 128];
__device__ float g_z2[BATCH * 128];
__device__ unsigned g_bar;

// ---------------------------------------------------------------------------
__device__ __forceinline__ uint32_t f2tf32(float x) {
    uint32_t r;
    asm("cvt.rna.tf32.f32 %0, %1;" : "=r"(r) : "f"(x));
    return r;
}

__device__ __forceinline__ void mma_tf32(float& c0, float& c1, float& c2, float& c3,
                                         uint32_t a0, uint32_t a1, uint32_t a2, uint32_t a3,
                                         uint32_t b0, uint32_t b1) {
    asm volatile(
        "mma.sync.aligned.m16n8k8.row.col.f32.tf32.tf32.f32 "
        "{%0,%1,%2,%3}, {%4,%5,%6,%7}, {%8,%9}, {%0,%1,%2,%3};"
        : "+f"(c0), "+f"(c1), "+f"(c2), "+f"(c3)
        : "r"(a0), "r"(a1), "r"(a2), "r"(a3), "r"(b0), "r"(b1));
}

// ---------------------------------------------------------------------------
// Grid-wide barrier (all NBLK CTAs co-resident).
// ---------------------------------------------------------------------------
__device__ __forceinline__ void grid_sync() {
    __syncthreads();
    if (threadIdx.x == 0) {
        __threadfence();
        unsigned old = atomicAdd(&g_bar, 1u);
        unsigned target = (old / NBLK + 1u) * NBLK;
        while (*((volatile unsigned*)&g_bar) < target) { }
        __threadfence();
    }
    __syncthreads();
}

// ---------------------------------------------------------------------------
// Init: start token, h0/c0, barrier reset, permuted tf32 weights, bias.
// Permutation: n' = b64*64 + g*16 + u  <->  original n = g*HID + b64*16 + u
// ---------------------------------------------------------------------------
__global__ void init_kernel(const float* __restrict__ hidden,
                            const float* __restrict__ W_ih,
                            const float* __restrict__ W_hh,
                            const float* __restrict__ b_ih,
                            const float* __restrict__ b_hh,
                            float* __restrict__ out) {
    int idx = blockIdx.x * blockDim.x + threadIdx.x;
    int stride = gridDim.x * blockDim.x;
    if (idx == 0) g_bar = 0u;

    for (int i = idx; i < BATCH * HID; i += stride) {
        g_h[0][i] = hidden[i];
        g_c[i] = 0.f;
    }
    for (int i = idx; i < BATCH * EMB; i += stride) {
        int b = i / EMB, e = i % EMB;
        out[(size_t)b * (SEQL * EMB) + e] = (e == 0) ? 1.f : 0.f;
    }
    for (int i = idx; i < G4H * KGATE; i += stride) {
        int np = i / KGATE, k = i % KGATE;
        int b64 = np >> 6, g = (np >> 4) & 3, u = np & 15;
        int n = g * HID + b64 * 16 + u;
        float v = (k < EMB) ? W_ih[n * EMB + k] : W_hh[n * HID + (k - EMB)];
        g_Wp[i] = __uint_as_float(f2tf32(v));
    }
    for (int i = idx; i < G4H; i += stride) {
        g_bc[i] = b_ih[i] + b_hh[i];
    }
}

// ---------------------------------------------------------------------------
// cp.async prefetch of one K-chunk (BK=16) of A (x|h) and B (permuted W).
// Each thread issues 2x16B for A and 2x16B for B.
// smem layout: s[buf*SBUF + row*SROW + k], rows 0..127, k 0..15.
// ---------------------------------------------------------------------------
__device__ __forceinline__ void gates_prefetch(float* sA, float* sB, int buf, int ci,
                                               const float* __restrict__ pts, int t,
                                               int mb, int nb,
                                               const float* __restrict__ hsrc) {
    const int tid = threadIdx.x;
    const int kc = ci * BK;
#pragma unroll
    for (int j = 0; j < 2; j++) {
        int idx = tid + j * NTHR;
        int m = idx >> 2, kq = (idx & 3) * 4;
        const float* srcA = (kc < EMB)
            ? (pts + (size_t)(mb + m) * (SEQL * EMB) + (size_t)t * EMB + kc + kq)
            : (hsrc + (size_t)(mb + m) * HID + (kc - EMB) + kq);
        unsigned dA = (unsigned)__cvta_generic_to_shared(sA + buf * SBUF + m * SROW + kq);
        asm volatile("cp.async.ca.shared.global [%0], [%1], 16;\n" :: "r"(dA), "l"(srcA));
        const float* srcB = g_Wp + (size_t)(nb + m) * KGATE + kc + kq;
        unsigned dB = (unsigned)__cvta_generic_to_shared(sB + buf * SBUF + m * SROW + kq);
        asm volatile("cp.async.ca.shared.global [%0], [%1], 16;\n" :: "r"(dB), "l"(srcB));
    }
}

// ---------------------------------------------------------------------------
// Phase A: gates GEMM 128x128 tile per CTA (tf32 mma) + fused LSTM epilogue.
// 8 warps as 4x2; warp tile 32 rows x 64 cols; mma m16n8k8.
// ---------------------------------------------------------------------------
__device__ void phase_gates(const float* __restrict__ pts, int t, int cur,
                            float* smem) {
    const int tile = blockIdx.x;
    const int mb = (tile >> 4) * 128;
    const int nb = (tile & 15) * 128;
    const int tid = threadIdx.x;
    const int lane = tid & 31, wid = tid >> 5;
    const int wr = wid >> 1, wc = wid & 1;
    const int gid = lane >> 2, tig = lane & 3;

    float* sA = smem;                  // 2 buffers of [128][SROW]
    float* sB = smem + 2 * SBUF;

    const float* hsrc = g_h[cur];

    float acc[2][8][4];
#pragma unroll
    for (int mt = 0; mt < 2; mt++)
#pragma unroll
        for (int nt = 0; nt < 8; nt++)
#pragma unroll
            for (int r = 0; r < 4; r++) acc[mt][nt][r] = 0.f;

    gates_prefetch(sA, sB, 0, 0, pts, t, mb, nb, hsrc);
    asm volatile("cp.async.commit_group;\n" ::: "memory");

    for (int ci = 0; ci < NCHUNK; ci++) {
        if (ci < NCHUNK - 1) {
            gates_prefetch(sA, sB, (ci + 1) & 1, ci + 1, pts, t, mb, nb, hsrc);
            asm volatile("cp.async.commit_group;\n" ::: "memory");
            asm volatile("cp.async.wait_group 1;\n" ::: "memory");
        } else {
            asm volatile("cp.async.wait_group 0;\n" ::: "memory");
        }
        __syncthreads();

        const int buf = ci & 1;
        const float* bufA = sA + buf * SBUF;
        const float* bufB = sB + buf * SBUF;
#pragma unroll
        for (int ks = 0; ks < 2; ks++) {
            const int ko = ks * 8;
            // B fragments: b0 = Wp[n][k=tig], b1 = Wp[n][k=tig+4]
            uint32_t bf[8][2];
#pragma unroll
            for (int nt = 0; nt < 8; nt++) {
                int n = wc * 64 + nt * 8 + gid;
                bf[nt][0] = __float_as_uint(bufB[n * SROW + ko + tig]);
                bf[nt][1] = __float_as_uint(bufB[n * SROW + ko + tig + 4]);
            }
#pragma unroll
            for (int mt = 0; mt < 2; mt++) {
                const int ar = wr * 32 + mt * 16;
                uint32_t a0 = f2tf32(bufA[(ar + gid) * SROW + ko + tig]);
                uint32_t a1 = f2tf32(bufA[(ar + 8 + gid) * SROW + ko + tig]);
                uint32_t a2 = f2tf32(bufA[(ar + gid) * SROW + ko + tig + 4]);
                uint32_t a3 = f2tf32(bufA[(ar + 8 + gid) * SROW + ko + tig + 4]);
#pragma unroll
                for (int nt = 0; nt < 8; nt++)
                    mma_tf32(acc[mt][nt][0], acc[mt][nt][1], acc[mt][nt][2], acc[mt][nt][3],
                             a0, a1, a2, a3, bf[nt][0], bf[nt][1]);
            }
        }
        __syncthreads();
    }

    // Fused LSTM epilogue. Col loc within 64-block = nt*8 + 2*tig + c;
    // gate = loc>>4 (nt pairs), unit u = loc&15. Thread-local quadruples:
    // unit u = wh*8 + 2*tig + c has its 4 gates at nt = {wh, 2+wh, 4+wh, 6+wh}.
    float* hn = g_h[cur ^ 1];
    const int b64 = (nb >> 6) + wc;
#pragma unroll
    for (int mt = 0; mt < 2; mt++) {
#pragma unroll
        for (int rh = 0; rh < 2; rh++) {
            const int m = mb + wr * 32 + mt * 16 + rh * 8 + gid;
#pragma unroll
            for (int c = 0; c < 2; c++) {
#pragma unroll
                for (int wh = 0; wh < 2; wh++) {
                    const int u = wh * 8 + 2 * tig + c;
                    const int j = b64 * 16 + u;
                    const int r = rh * 2 + c;
                    float gi = acc[mt][0 + wh][r] + g_bc[j];
                    float gf = acc[mt][2 + wh][r] + g_bc[HID + j];
                    float gg = acc[mt][4 + wh][r] + g_bc[2 * HID + j];
                    float go = acc[mt][6 + wh][r] + g_bc[3 * HID + j];
                    float ii = 1.f / (1.f + __expf(-gi));
                    float ff = 1.f / (1.f + __expf(-gf));
                    float tg = tanhf(gg);
                    float oo = 1.f / (1.f + __expf(-go));
                    float cn = ff * g_c[m * HID + j] + ii * tg;
                    g_c[m * HID + j] = cn;
                    hn[m * HID + j] = oo * tanhf(cn);
                }
            }
        }
    }
}

// ---------------------------------------------------------------------------
// Small FFMA GEMM for the MLP layers (unchanged from baseline).
// ---------------------------------------------------------------------------
template <int N, int K, bool RELU>
__device__ void mlp_gemm(const float* __restrict__ Ain, int ldA,
                         const float* __restrict__ W,
                         const float* __restrict__ bias,
                         float* __restrict__ Cout, int ldC, float* smem) {
    float* sA = smem;              // [16][33]
    float* sB = smem + 16 * 33;    // [16][33]
    const int tid = threadIdx.x;
    const int tx = tid & 15, ty = tid >> 4;
    const int ncolt = N / 32;
    const int ntiles = (BATCH / 32) * ncolt;

    for (int tile = blockIdx.x; tile < ntiles; tile += NBLK) {
        int mb = (tile / ncolt) * 32;
        int nb = (tile % ncolt) * 32;
        float acc00 = 0.f, acc01 = 0.f, acc10 = 0.f, acc11 = 0.f;
        for (int kc = 0; kc < K; kc += 16) {
            int k = tid & 15, r = tid >> 4;
            sA[k * 33 + r]      = Ain[(mb + r) * ldA + kc + k];
            sA[k * 33 + r + 16] = Ain[(mb + r + 16) * ldA + kc + k];
            sB[k * 33 + r]      = W[(nb + r) * K + kc + k];
            sB[k * 33 + r + 16] = W[(nb + r + 16) * K + kc + k];
            __syncthreads();
#pragma unroll
            for (int kk = 0; kk < 16; kk++) {
                float a0 = sA[kk * 33 + ty * 2];
                float a1 = sA[kk * 33 + ty * 2 + 1];
                float b0 = sB[kk * 33 + tx * 2];
                float b1 = sB[kk * 33 + tx * 2 + 1];
                acc00 += a0 * b0; acc01 += a0 * b1;
                acc10 += a1 * b0; acc11 += a1 * b1;
            }
            __syncthreads();
        }
        {
            int m0 = mb + ty * 2, n0 = nb + tx * 2;
            float v00 = acc00 + bias[n0];
            float v01 = acc01 + bias[n0 + 1];
            float v10 = acc10 + bias[n0];
            float v11 = acc11 + bias[n0 + 1];
            if (RELU) {
                v00 = fmaxf(v00, 0.f); v01 = fmaxf(v01, 0.f);
                v10 = fmaxf(v10, 0.f); v11 = fmaxf(v11, 0.f);
            }
            Cout[(size_t)m0 * ldC + n0]           = v00;
            Cout[(size_t)m0 * ldC + n0 + 1]       = v01;
            Cout[(size_t)(m0 + 1) * ldC + n0]     = v10;
            Cout[(size_t)(m0 + 1) * ldC + n0 + 1] = v11;
        }
    }
}

// ---------------------------------------------------------------------------
// Persistent kernel: 127 steps, 3 grid syncs per step.
// ---------------------------------------------------------------------------
__global__ void __launch_bounds__(NTHR, 1)
lstm_kernel(const float* __restrict__ pts,
            const float* __restrict__ W1, const float* __restrict__ b1,
            const float* __restrict__ W2, const float* __restrict__ b2,
            const float* __restrict__ W3, const float* __restrict__ b3,
            float* __restrict__ out) {
    __shared__ __align__(16) float smem[4 * SBUF];   // 40 KB, aliased by MLP
    int cur = 0;
    for (int t = 0; t < STEPS; t++) {
        phase_gates(pts, t, cur, smem);
        grid_sync();
        int nxt = cur ^ 1;
        mlp_gemm<128, HID, true>(g_h[nxt], HID, W1, b1, g_z1, 128, smem);
        grid_sync();
        mlp_gemm<128, 128, true>(g_z1, 128, W2, b2, g_z2, 128, smem);
        grid_sync();
        mlp_gemm<EMB, 128, false>(g_z2, 128, W3, b3,
                                  out + (size_t)(t + 1) * EMB, SEQL * EMB, smem);
        cur = nxt;
    }
}

// ---------------------------------------------------------------------------
extern "C" void kernel_launch(void* const* d_in, const int* in_sizes, int n_in,
                              void* d_out, int out_size) {
    (void)in_sizes; (void)n_in; (void)out_size;
    const float* hidden = (const float*)d_in[0];
    const float* pts    = (const float*)d_in[1];
    const float* W_ih   = (const float*)d_in[2];
    const float* W_hh   = (const float*)d_in[3];
    const float* b_ih   = (const float*)d_in[4];
    const float* b_hh   = (const float*)d_in[5];
    const float* W1     = (const float*)d_in[6];
    const float* b1     = (const float*)d_in[7];
    const float* W2     = (const float*)d_in[8];
    const float* b2     = (const float*)d_in[9];
    const float* W3     = (const float*)d_in[10];
    const float* b3     = (const float*)d_in[11];
    float* out = (float*)d_out;

    init_kernel<<<256, 256>>>(hidden, W_ih, W_hh, b_ih, b_hh, out);
    lstm_kernel<<<NBLK, NTHR>>>(pts, W1, b1, W2, b2, W3, b3, out);
}

// round 5
// speedup vs baseline: 2.9004x; 1.6590x over previous
#include <cuda_runtime.h>
#include <math.h>
#include <stdint.h>

// ---------------------------------------------------------------------------
// SpecDecoder: 127-step LSTM + 3-layer MLP decoder, all GEMMs on mma.sync tf32.
// B=1024, H=512, E=256, L=128.  (tcgen05 unavailable: harness targets sm_100.)
// ---------------------------------------------------------------------------

#define BATCH 1024
#define HID   512
#define EMB   256
#define SEQL  128
#define STEPS (SEQL - 1)
#define G4H   2048
#define KGATE 768
#define NBLK  128
#define NTHR  512
#define BK    16
#define NCHUNK (KGATE / BK)    // 48
#define SROW  20               // gates smem row stride (floats)
#define STAGEF (2 * 128 * SROW)  // floats per stage (A+B)
#define DSMEM  136320          // max(gates 3*20480B, z1 staging 132096+red 4224)

// ---------------- device scratch --------------------------------------------
__device__ float g_Wp[G4H * KGATE];     // permuted tf32 gates weights [n'][k]
__device__ float g_bc[G4H];             // combined bias, ORIGINAL order
__device__ float g_W1p[128 * HID];      // tf32-rounded MLP weights
__device__ float g_W2p[128 * 128];
__device__ float g_W3p[EMB * 128];
__device__ float g_h[2][BATCH * HID];
__device__ float g_c[BATCH * HID];
__device__ float g_z1[BATCH * 128];
__device__ float g_z2[BATCH * 128];
__device__ unsigned g_bar;

// ---------------------------------------------------------------------------
__device__ __forceinline__ uint32_t f2tf32(float x) {
    uint32_t r;
    asm("cvt.rna.tf32.f32 %0, %1;" : "=r"(r) : "f"(x));
    return r;
}

__device__ __forceinline__ void mma_tf32(float& c0, float& c1, float& c2, float& c3,
                                         uint32_t a0, uint32_t a1, uint32_t a2, uint32_t a3,
                                         uint32_t b0, uint32_t b1) {
    asm volatile(
        "mma.sync.aligned.m16n8k8.row.col.f32.tf32.tf32.f32 "
        "{%0,%1,%2,%3}, {%4,%5,%6,%7}, {%8,%9}, {%0,%1,%2,%3};"
        : "+f"(c0), "+f"(c1), "+f"(c2), "+f"(c3)
        : "r"(a0), "r"(a1), "r"(a2), "r"(a3), "r"(b0), "r"(b1));
}

#define CP_ASYNC16(dst, src) \
    asm volatile("cp.async.ca.shared.global [%0], [%1], 16;\n" :: "r"(dst), "l"(src))
#define CP_COMMIT() asm volatile("cp.async.commit_group;\n" ::: "memory")

__device__ __forceinline__ void grid_sync() {
    __syncthreads();
    if (threadIdx.x == 0) {
        __threadfence();
        unsigned old = atomicAdd(&g_bar, 1u);
        unsigned target = (old / NBLK + 1u) * NBLK;
        while (*((volatile unsigned*)&g_bar) < target) { }
        __threadfence();
    }
    __syncthreads();
}

// ---------------------------------------------------------------------------
// Init. Gate permutation: n' = b8*32 + g*8 + u  <->  n = g*HID + b8*8 + u
// ---------------------------------------------------------------------------
__global__ void init_kernel(const float* __restrict__ hidden,
                            const float* __restrict__ W_ih,
                            const float* __restrict__ W_hh,
                            const float* __restrict__ b_ih,
                            const float* __restrict__ b_hh,
                            const float* __restrict__ W1,
                            const float* __restrict__ W2,
                            const float* __restrict__ W3,
                            float* __restrict__ out) {
    int idx = blockIdx.x * blockDim.x + threadIdx.x;
    int stride = gridDim.x * blockDim.x;
    if (idx == 0) g_bar = 0u;

    for (int i = idx; i < BATCH * HID; i += stride) {
        g_h[0][i] = __uint_as_float(f2tf32(hidden[i]));
        g_c[i] = 0.f;
    }
    for (int i = idx; i < BATCH * EMB; i += stride) {
        int b = i / EMB, e = i % EMB;
        out[(size_t)b * (SEQL * EMB) + e] = (e == 0) ? 1.f : 0.f;
    }
    for (int i = idx; i < G4H * KGATE; i += stride) {
        int np = i / KGATE, k = i % KGATE;
        int b8 = np >> 5, g = (np >> 3) & 3, u = np & 7;
        int n = g * HID + b8 * 8 + u;
        float v = (k < EMB) ? W_ih[n * EMB + k] : W_hh[n * HID + (k - EMB)];
        g_Wp[i] = __uint_as_float(f2tf32(v));
    }
    for (int i = idx; i < G4H; i += stride) g_bc[i] = b_ih[i] + b_hh[i];
    for (int i = idx; i < 128 * HID; i += stride)
        g_W1p[i] = __uint_as_float(f2tf32(W1[i]));
    for (int i = idx; i < 128 * 128; i += stride)
        g_W2p[i] = __uint_as_float(f2tf32(W2[i]));
    for (int i = idx; i < EMB * 128; i += stride)
        g_W3p[i] = __uint_as_float(f2tf32(W3[i]));
}

// ---------------------------------------------------------------------------
// Gates: prefetch one K-chunk (128 rows x 16 k of A and B) into a stage.
// 512 threads: each issues one 16B cp.async for A and one for B.
// ---------------------------------------------------------------------------
__device__ __forceinline__ void gates_pf(float* dsm, int ci,
                                         const float* __restrict__ pts, int t,
                                         int mb, int nb,
                                         const float* __restrict__ hsrc) {
    const int tid = threadIdx.x;
    float* stage = dsm + (ci % 3) * STAGEF;
    const int row = tid >> 2, kq = (tid & 3) * 4;
    const int k = ci * BK + kq;
    const float* srcA = (k < EMB)
        ? (pts + (size_t)(mb + row) * (SEQL * EMB) + (size_t)t * EMB + k)
        : (hsrc + (size_t)(mb + row) * HID + (k - EMB));
    unsigned dA = (unsigned)__cvta_generic_to_shared(stage + row * SROW + kq);
    CP_ASYNC16(dA, srcA);
    const float* srcB = g_Wp + (size_t)(nb + row) * KGATE + k;
    unsigned dB = (unsigned)__cvta_generic_to_shared(stage + 128 * SROW + row * SROW + kq);
    CP_ASYNC16(dB, srcB);
    CP_COMMIT();
}

// ---------------------------------------------------------------------------
// Phase A: gates GEMM 128x128 tile (16 warps, 4x4 grid, warp tile 32x32),
// 3-stage cp.async pipeline, fused LSTM epilogue.
// ---------------------------------------------------------------------------
__device__ void phase_gates(const float* __restrict__ pts, int t, int cur,
                            float* dsm) {
    const int tile = blockIdx.x;
    const int mb = (tile >> 4) * 128;
    const int nb = (tile & 15) * 128;
    const int tid = threadIdx.x;
    const int lane = tid & 31, wid = tid >> 5;
    const int wr = wid >> 2, wc = wid & 3;
    const int gid = lane >> 2, tig = lane & 3;
    const float* hsrc = g_h[cur];

    float acc[2][4][4];
#pragma unroll
    for (int mt = 0; mt < 2; mt++)
#pragma unroll
        for (int nt = 0; nt < 4; nt++)
#pragma unroll
            for (int r = 0; r < 4; r++) acc[mt][nt][r] = 0.f;

    gates_pf(dsm, 0, pts, t, mb, nb, hsrc);
    gates_pf(dsm, 1, pts, t, mb, nb, hsrc);

    for (int ci = 0; ci < NCHUNK; ci++) {
        if (ci + 2 < NCHUNK) {
            gates_pf(dsm, ci + 2, pts, t, mb, nb, hsrc);
            asm volatile("cp.async.wait_group 2;\n" ::: "memory");
        } else if (ci + 1 < NCHUNK) {
            asm volatile("cp.async.wait_group 1;\n" ::: "memory");
        } else {
            asm volatile("cp.async.wait_group 0;\n" ::: "memory");
        }
        __syncthreads();

        const float* stage = dsm + (ci % 3) * STAGEF;
        const float* bufA = stage;
        const float* bufB = stage + 128 * SROW;
#pragma unroll
        for (int ks = 0; ks < 2; ks++) {
            const int ko = ks * 8;
            uint32_t bf[4][2];
#pragma unroll
            for (int nt = 0; nt < 4; nt++) {
                int n = wc * 32 + nt * 8 + gid;
                bf[nt][0] = __float_as_uint(bufB[n * SROW + ko + tig]);
                bf[nt][1] = __float_as_uint(bufB[n * SROW + ko + tig + 4]);
            }
#pragma unroll
            for (int mt = 0; mt < 2; mt++) {
                const int ar = wr * 32 + mt * 16;
                uint32_t a0 = f2tf32(bufA[(ar + gid) * SROW + ko + tig]);
                uint32_t a1 = f2tf32(bufA[(ar + 8 + gid) * SROW + ko + tig]);
                uint32_t a2 = f2tf32(bufA[(ar + gid) * SROW + ko + tig + 4]);
                uint32_t a3 = f2tf32(bufA[(ar + 8 + gid) * SROW + ko + tig + 4]);
#pragma unroll
                for (int nt = 0; nt < 4; nt++)
                    mma_tf32(acc[mt][nt][0], acc[mt][nt][1], acc[mt][nt][2], acc[mt][nt][3],
                             a0, a1, a2, a3, bf[nt][0], bf[nt][1]);
            }
        }
        __syncthreads();
    }

    // Fused LSTM epilogue. Warp col block = 32 permuted cols = units
    // j in [jbase, jbase+8), gates nt=g at cols g*8+u, u = 2*tig + {0,1}.
    float* hn = g_h[cur ^ 1];
    const int jbase = ((nb >> 5) + wc) * 8;
    const int jb = jbase + 2 * tig;
    float2 bi = *(const float2*)&g_bc[jb];
    float2 bff = *(const float2*)&g_bc[HID + jb];
    float2 bg = *(const float2*)&g_bc[2 * HID + jb];
    float2 bo = *(const float2*)&g_bc[3 * HID + jb];
#pragma unroll
    for (int mt = 0; mt < 2; mt++) {
#pragma unroll
        for (int rh = 0; rh < 2; rh++) {
            const int m = mb + wr * 32 + mt * 16 + rh * 8 + gid;
            float2 cv = *(const float2*)&g_c[(size_t)m * HID + jb];
            float cn[2], hh[2];
#pragma unroll
            for (int u = 0; u < 2; u++) {
                const int r = rh * 2 + u;
                float gi = acc[mt][0][r] + (u ? bi.y : bi.x);
                float gf = acc[mt][1][r] + (u ? bff.y : bff.x);
                float gg = acc[mt][2][r] + (u ? bg.y : bg.x);
                float go = acc[mt][3][r] + (u ? bo.y : bo.x);
                float ii = 1.f / (1.f + __expf(-gi));
                float ff = 1.f / (1.f + __expf(-gf));
                float tg = tanhf(gg);
                float oo = 1.f / (1.f + __expf(-go));
                cn[u] = ff * (u ? cv.y : cv.x) + ii * tg;
                hh[u] = __uint_as_float(f2tf32(oo * tanhf(cn[u])));
            }
            *(float2*)&g_c[(size_t)m * HID + jb] = make_float2(cn[0], cn[1]);
            *(float2*)&hn[(size_t)m * HID + jb]  = make_float2(hh[0], hh[1]);
        }
    }
}

// ---------------------------------------------------------------------------
// MLP layer on mma.sync tf32.  Tile = 32 rows x NCOLS cols per CTA
// (CTA -> m = bid>>2, n-quarter = bid&3).  A and W staged in smem.
// KSPLIT: 16 warps = 8 subtiles x 2 K-halves, reduced via smem.
// !KSPLIT (NCOLS=64): 16 warps = 16 subtiles, full K, no reduction.
// A and W are pre-rounded tf32 values stored as fp32.
// ---------------------------------------------------------------------------
template <int KD, int NCOLS, bool RELU, bool KSPLIT>
__device__ void mlp_mma(const float* __restrict__ Ag,
                        const float* __restrict__ Bg,
                        const float* __restrict__ bias,
                        float* __restrict__ Cg, int ldC, float* dsm) {
    const int bid = blockIdx.x;
    const int mb = (bid >> 2) * 32;
    const int nb = (bid & 3) * NCOLS;
    const int tid = threadIdx.x;
    const int lane = tid & 31, wid = tid >> 5;
    const int gid = lane >> 2, tig = lane & 3;
    constexpr int LDSR = KD + 4;
    float* sA = dsm;
    float* sB = sA + 32 * LDSR;
    float* red = sB + NCOLS * LDSR;

    // stage A tile (32 x KD) and B tile (NCOLS x KD)
    constexpr int AOPS = 32 * KD / 4;
#pragma unroll
    for (int i = tid; i < AOPS; i += NTHR) {
        int row = i / (KD / 4), seg = (i % (KD / 4)) * 4;
        unsigned d = (unsigned)__cvta_generic_to_shared(sA + row * LDSR + seg);
        CP_ASYNC16(d, Ag + (size_t)(mb + row) * KD + seg);
    }
    constexpr int BOPS = NCOLS * KD / 4;
#pragma unroll
    for (int i = tid; i < BOPS; i += NTHR) {
        int row = i / (KD / 4), seg = (i % (KD / 4)) * 4;
        unsigned d = (unsigned)__cvta_generic_to_shared(sB + row * LDSR + seg);
        CP_ASYNC16(d, Bg + (size_t)(nb + row) * KD + seg);
    }
    CP_COMMIT();
    asm volatile("cp.async.wait_group 0;\n" ::: "memory");
    __syncthreads();

    int mt, nt, kbase;
    if (KSPLIT) { int s = wid & 7; mt = s >> 2; nt = s & 3; kbase = (wid >> 3) * (KD / 2); }
    else        { mt = wid >> 3; nt = wid & 7; kbase = 0; }
    constexpr int KCNT = (KSPLIT ? KD / 2 : KD) / 8;

    float c0 = 0.f, c1 = 0.f, c2 = 0.f, c3 = 0.f;
    const float* arow = sA + (mt * 16 + gid) * LDSR;
    const float* brow = sB + (nt * 8 + gid) * LDSR;
#pragma unroll
    for (int ks = 0; ks < KCNT; ks++) {
        const int k0 = kbase + ks * 8;
        uint32_t a0 = __float_as_uint(arow[k0 + tig]);
        uint32_t a1 = __float_as_uint(arow[8 * LDSR + k0 + tig]);
        uint32_t a2 = __float_as_uint(arow[k0 + tig + 4]);
        uint32_t a3 = __float_as_uint(arow[8 * LDSR + k0 + tig + 4]);
        uint32_t b0 = __float_as_uint(brow[k0 + tig]);
        uint32_t b1 = __float_as_uint(brow[k0 + tig + 4]);
        mma_tf32(c0, c1, c2, c3, a0, a1, a2, a3, b0, b1);
    }

    bool do_epi = true;
    if (KSPLIT) {
        const int r0 = (mt * 16 + gid) * 33 + nt * 8 + 2 * tig;
        if (wid >= 8) {
            red[r0] = c0; red[r0 + 1] = c1;
            red[r0 + 8 * 33] = c2; red[r0 + 8 * 33 + 1] = c3;
        }
        __syncthreads();
        if (wid < 8) {
            c0 += red[r0]; c1 += red[r0 + 1];
            c2 += red[r0 + 8 * 33]; c3 += red[r0 + 8 * 33 + 1];
        } else {
            do_epi = false;
        }
    }
    if (do_epi) {
        const int n0 = nb + nt * 8 + 2 * tig;
        float2 bs = *(const float2*)&bias[n0];
        float v0 = c0 + bs.x, v1 = c1 + bs.y;
        float v2 = c2 + bs.x, v3 = c3 + bs.y;
        if (RELU) {
            v0 = fmaxf(v0, 0.f); v1 = fmaxf(v1, 0.f);
            v2 = fmaxf(v2, 0.f); v3 = fmaxf(v3, 0.f);
            // round activations so the next tf32 GEMM needs no cvt
            v0 = __uint_as_float(f2tf32(v0)); v1 = __uint_as_float(f2tf32(v1));
            v2 = __uint_as_float(f2tf32(v2)); v3 = __uint_as_float(f2tf32(v3));
        }
        const int m0 = mb + mt * 16 + gid;
        *(float2*)&Cg[(size_t)m0 * ldC + n0]       = make_float2(v0, v1);
        *(float2*)&Cg[(size_t)(m0 + 8) * ldC + n0] = make_float2(v2, v3);
    }
}

// ---------------------------------------------------------------------------
// Persistent kernel: 127 steps, 3 grid syncs per step.
// ---------------------------------------------------------------------------
__global__ void __launch_bounds__(NTHR, 1)
lstm_kernel(const float* __restrict__ pts,
            const float* __restrict__ b1,
            const float* __restrict__ b2,
            const float* __restrict__ b3,
            float* __restrict__ out) {
    extern __shared__ __align__(16) float dsm[];
    int cur = 0;
    for (int t = 0; t < STEPS; t++) {
        phase_gates(pts, t, cur, dsm);
        grid_sync();
        int nxt = cur ^ 1;
        mlp_mma<HID, 32, true, true>(g_h[nxt], g_W1p, b1, g_z1, 128, dsm);
        grid_sync();
        mlp_mma<128, 32, true, true>(g_z1, g_W2p, b2, g_z2, 128, dsm);
        grid_sync();
        mlp_mma<128, 64, false, false>(g_z2, g_W3p, b3,
                                       out + (size_t)(t + 1) * EMB, SEQL * EMB, dsm);
        __syncthreads();   // guard smem reuse by next step's gates prefetch
        cur = nxt;
    }
}

// ---------------------------------------------------------------------------
extern "C" void kernel_launch(void* const* d_in, const int* in_sizes, int n_in,
                              void* d_out, int out_size) {
    (void)in_sizes; (void)n_in; (void)out_size;
    const float* hidden = (const float*)d_in[0];
    const float* pts    = (const float*)d_in[1];
    const float* W_ih   = (const float*)d_in[2];
    const float* W_hh   = (const float*)d_in[3];
    const float* b_ih   = (const float*)d_in[4];
    const float* b_hh   = (const float*)d_in[5];
    const float* W1     = (const float*)d_in[6];
    const float* b1     = (const float*)d_in[7];
    const float* W2     = (const float*)d_in[8];
    const float* b2     = (const float*)d_in[9];
    const float* W3     = (const float*)d_in[10];
    const float* b3     = (const float*)d_in[11];
    float* out = (float*)d_out;

    cudaFuncSetAttribute(lstm_kernel, cudaFuncAttributeMaxDynamicSharedMemorySize, DSMEM);
    init_kernel<<<256, 256>>>(hidden, W_ih, W_hh, b_ih, b_hh, W1, W2, W3, out);
    lstm_kernel<<<NBLK, NTHR, DSMEM>>>(pts, b1, b2, b3, out);
}

// round 6
// speedup vs baseline: 3.8874x; 1.3403x over previous
#include <cuda_runtime.h>
#include <math.h>
#include <stdint.h>

// ---------------------------------------------------------------------------
// SpecDecoder: 127-step LSTM + fused 3-layer MLP, all GEMMs mma.sync tf32.
// Fragment-major storage for every operand; one grid sync per step.
// B=1024, H=512, E=256, L=128.
// ---------------------------------------------------------------------------

#define BATCH 1024
#define HID   512
#define EMB   256
#define SEQL  128
#define STEPS (SEQL - 1)
#define NBLK  128
#define NTHR  256
#define NCHUNK 24              // BK=32 chunks over KGATE=768
#define DSMEM 122880           // 3*32KB gates stages + 16+4+4KB MLP

// ---------------- device scratch (frag-major: [..][lane 0..31][float4]) -----
// float4 value for lane (gid=lane>>2, tig=lane&3) = elem k = base + tig + 4s
__device__ float4 g_xf4[8388608];      // [t][kc 0..15][m8 0..127][lane]  (134MB)
__device__ float4 g_hf4[2][131072];    // [kc 0..31][m8 0..127][lane]
__device__ float4 g_Wf4[393216];       // [kc 0..47][n8' 0..255][lane]
__device__ float4 g_W1f4[16384];       // [n8 0..15][kc 0..31][lane]
__device__ float4 g_W2f4[4096];        // [n8 0..15][kc 0..7][lane]
__device__ float4 g_W3f4[8192];        // [n8 0..31][kc 0..7][lane]
__device__ float  g_bc[2048];          // combined LSTM bias, original order
__device__ float  g_c[BATCH * HID];    // cell state, row-major
__device__ unsigned g_bar;

// ---------------------------------------------------------------------------
__device__ __forceinline__ float tfr(float x) {   // round-to-nearest tf32
    uint32_t r;
    asm("cvt.rna.tf32.f32 %0, %1;" : "=r"(r) : "f"(x));
    return __uint_as_float(r);
}

__device__ __forceinline__ void mma_tf32(float& c0, float& c1, float& c2, float& c3,
                                         uint32_t a0, uint32_t a1, uint32_t a2, uint32_t a3,
                                         uint32_t b0, uint32_t b1) {
    asm volatile(
        "mma.sync.aligned.m16n8k8.row.col.f32.tf32.tf32.f32 "
        "{%0,%1,%2,%3}, {%4,%5,%6,%7}, {%8,%9}, {%0,%1,%2,%3};"
        : "+f"(c0), "+f"(c1), "+f"(c2), "+f"(c3)
        : "r"(a0), "r"(a1), "r"(a2), "r"(a3), "r"(b0), "r"(b1));
}

#define CP_ASYNC16(dst, src) \
    asm volatile("cp.async.ca.shared.global [%0], [%1], 16;\n" :: "r"(dst), "l"(src))
#define CP_COMMIT() asm volatile("cp.async.commit_group;\n" ::: "memory")

__device__ __forceinline__ float fast_sig(float x) {
    return __fdividef(1.f, 1.f + __expf(-x));
}
__device__ __forceinline__ float fast_tanh(float x) {
    return 1.f - __fdividef(2.f, __expf(2.f * x) + 1.f);
}

__device__ __forceinline__ void grid_sync() {
    __syncthreads();
    if (threadIdx.x == 0) {
        __threadfence();                       // release + L1 flush
        unsigned old = atomicAdd(&g_bar, 1u);
        unsigned target = (old / NBLK + 1u) * NBLK;
        while (*((volatile unsigned*)&g_bar) < target) { }
        __threadfence();                       // acquire + L1 flush
    }
    __syncthreads();
}

// ---------------------------------------------------------------------------
// Init: build every frag-major tensor. Gate permutation: permuted col
// n' = b8*32 + g*8 + u  <->  original row n = g*HID + b8*8 + u.
// ---------------------------------------------------------------------------
__global__ void init_kernel(const float* __restrict__ hidden,
                            const float* __restrict__ pts,
                            const float* __restrict__ W_ih,
                            const float* __restrict__ W_hh,
                            const float* __restrict__ b_ih,
                            const float* __restrict__ b_hh,
                            const float* __restrict__ W1,
                            const float* __restrict__ W2,
                            const float* __restrict__ W3,
                            float* __restrict__ out) {
    const int idx0 = blockIdx.x * blockDim.x + threadIdx.x;
    const int stride = gridDim.x * blockDim.x;
    if (idx0 == 0) g_bar = 0u;

    // x frag-major
    for (int q = idx0; q < 8388608; q += stride) {
        int lane = q & 31, m8 = (q >> 5) & 127, kc = (q >> 12) & 15, t = q >> 16;
        int gid = lane >> 2, tig = lane & 3;
        const float* p = pts + (size_t)(m8 * 8 + gid) * (SEQL * EMB)
                             + (size_t)t * EMB + kc * 16 + tig;
        g_xf4[q] = make_float4(tfr(p[0]), tfr(p[4]), tfr(p[8]), tfr(p[12]));
    }
    // h0 frag-major
    for (int q = idx0; q < 131072; q += stride) {
        int lane = q & 31, m8 = (q >> 5) & 127, kc = q >> 12;
        int gid = lane >> 2, tig = lane & 3;
        const float* p = hidden + (size_t)(m8 * 8 + gid) * HID + kc * 16 + tig;
        g_hf4[0][q] = make_float4(tfr(p[0]), tfr(p[4]), tfr(p[8]), tfr(p[12]));
    }
    // gates W frag-major (permuted)
    for (int q = idx0; q < 393216; q += stride) {
        int lane = q & 31, n8 = (q >> 5) & 255, kc = q >> 13;
        int gid = lane >> 2, tig = lane & 3;
        int b8 = n8 >> 2, g = n8 & 3;
        int n = g * HID + b8 * 8 + gid;
        int k = kc * 16 + tig;
        float v[4];
#pragma unroll
        for (int s = 0; s < 4; s++) {
            int kk = k + 4 * s;
            v[s] = (kk < EMB) ? W_ih[(size_t)n * EMB + kk]
                              : W_hh[(size_t)n * HID + (kk - EMB)];
        }
        g_Wf4[q] = make_float4(tfr(v[0]), tfr(v[1]), tfr(v[2]), tfr(v[3]));
    }
    // MLP weights frag-major
    for (int q = idx0; q < 16384; q += stride) {
        int lane = q & 31, kc = (q >> 5) & 31, n8 = q >> 10;
        int gid = lane >> 2, tig = lane & 3;
        const float* p = W1 + (size_t)(n8 * 8 + gid) * HID + kc * 16 + tig;
        g_W1f4[q] = make_float4(tfr(p[0]), tfr(p[4]), tfr(p[8]), tfr(p[12]));
    }
    for (int q = idx0; q < 4096; q += stride) {
        int lane = q & 31, kc = (q >> 5) & 7, n8 = q >> 8;
        int gid = lane >> 2, tig = lane & 3;
        const float* p = W2 + (size_t)(n8 * 8 + gid) * 128 + kc * 16 + tig;
        g_W2f4[q] = make_float4(tfr(p[0]), tfr(p[4]), tfr(p[8]), tfr(p[12]));
    }
    for (int q = idx0; q < 8192; q += stride) {
        int lane = q & 31, kc = (q >> 5) & 7, n8 = q >> 8;
        int gid = lane >> 2, tig = lane & 3;
        const float* p = W3 + (size_t)(n8 * 8 + gid) * 128 + kc * 16 + tig;
        g_W3f4[q] = make_float4(tfr(p[0]), tfr(p[4]), tfr(p[8]), tfr(p[12]));
    }
    for (int i = idx0; i < BATCH * HID; i += stride) g_c[i] = 0.f;
    for (int i = idx0; i < 2048; i += stride) g_bc[i] = b_ih[i] + b_hh[i];
    for (int i = idx0; i < BATCH * EMB; i += stride) {
        int b = i / EMB, e = i % EMB;
        out[(size_t)b * (SEQL * EMB) + e] = (e == 0) ? 1.f : 0.f;
    }
}

// ---------------------------------------------------------------------------
// Gates prefetch: one BK=32 chunk = 32KB (A 16KB + B 16KB) into stage ci%3.
// Sources are frag-major, so every copy is contiguous 16B.
// ---------------------------------------------------------------------------
__device__ __forceinline__ void gates_pf(float* dsm, int ci, int t,
                                         int m8b, int n8b, const float4* hf) {
    const int tid = threadIdx.x;
    float* stage = dsm + (ci % 3) * 8192;
#pragma unroll
    for (int j = 0; j < 8; j++) {
        int u = j * 256 + tid;                 // 16B unit 0..2047
        unsigned dst = (unsigned)__cvta_generic_to_shared(stage + u * 4);
        const float4* src;
        if (u < 1024) {                        // A
            int kc2 = u >> 9, r = u & 511, grp = r >> 5, ln = r & 31;
            int kc = ci * 2 + kc2;
            src = (kc < 16)
                ? (g_xf4 + (((size_t)(t * 16 + kc) * 128 + m8b + grp) << 5) + ln)
                : (hf + (((size_t)(kc - 16) * 128 + m8b + grp) << 5) + ln);
        } else {                               // B
            int u2 = u - 1024;
            int kc2 = u2 >> 9, r = u2 & 511, grp = r >> 5, ln = r & 31;
            src = g_Wf4 + (((size_t)(ci * 2 + kc2) * 256 + n8b + grp) << 5) + ln;
        }
        CP_ASYNC16(dst, src);
    }
    CP_COMMIT();
}

// ---------------------------------------------------------------------------
// Gates: 128x128 CTA tile, 8 warps (2x4), warp tile 64x32, fused LSTM epi.
// ---------------------------------------------------------------------------
__device__ void phase_gates(int t, int cur, float* dsm) {
    const int tile = blockIdx.x;
    const int m8b = (tile >> 4) * 16, n8b = (tile & 15) * 16;
    const int tid = threadIdx.x, lane = tid & 31, wid = tid >> 5;
    const int wr = wid >> 2, wc = wid & 3;
    const int gid = lane >> 2, tig = lane & 3;
    const float4* hf = g_hf4[cur];

    float acc[4][4][4];
#pragma unroll
    for (int mt = 0; mt < 4; mt++)
#pragma unroll
        for (int nt = 0; nt < 4; nt++)
#pragma unroll
            for (int r = 0; r < 4; r++) acc[mt][nt][r] = 0.f;

    gates_pf(dsm, 0, t, m8b, n8b, hf);
    gates_pf(dsm, 1, t, m8b, n8b, hf);

#pragma unroll 1
    for (int ci = 0; ci < NCHUNK; ci++) {
        if (ci + 2 < NCHUNK) {
            gates_pf(dsm, ci + 2, t, m8b, n8b, hf);
            asm volatile("cp.async.wait_group 2;\n" ::: "memory");
        } else if (ci + 1 < NCHUNK) {
            asm volatile("cp.async.wait_group 1;\n" ::: "memory");
        } else {
            asm volatile("cp.async.wait_group 0;\n" ::: "memory");
        }
        __syncthreads();

        const float* sA = dsm + (ci % 3) * 8192;
        const float* sB = sA + 4096;
#pragma unroll
        for (int kc2 = 0; kc2 < 2; kc2++) {
            float4 af[8];
#pragma unroll
            for (int g8 = 0; g8 < 8; g8++)
                af[g8] = *(const float4*)&sA[(((kc2 * 16) + wr * 8 + g8) * 32 + lane) * 4];
            float4 bf[4];
#pragma unroll
            for (int nb = 0; nb < 4; nb++)
                bf[nb] = *(const float4*)&sB[(((kc2 * 16) + wc * 4 + nb) * 32 + lane) * 4];
#pragma unroll
            for (int mt = 0; mt < 4; mt++) {
                uint32_t a0 = __float_as_uint(af[2 * mt].x), a1 = __float_as_uint(af[2 * mt + 1].x);
                uint32_t a2 = __float_as_uint(af[2 * mt].y), a3 = __float_as_uint(af[2 * mt + 1].y);
                uint32_t e0 = __float_as_uint(af[2 * mt].z), e1 = __float_as_uint(af[2 * mt + 1].z);
                uint32_t e2 = __float_as_uint(af[2 * mt].w), e3 = __float_as_uint(af[2 * mt + 1].w);
#pragma unroll
                for (int nt = 0; nt < 4; nt++) {
                    mma_tf32(acc[mt][nt][0], acc[mt][nt][1], acc[mt][nt][2], acc[mt][nt][3],
                             a0, a1, a2, a3,
                             __float_as_uint(bf[nt].x), __float_as_uint(bf[nt].y));
                    mma_tf32(acc[mt][nt][0], acc[mt][nt][1], acc[mt][nt][2], acc[mt][nt][3],
                             e0, e1, e2, e3,
                             __float_as_uint(bf[nt].z), __float_as_uint(bf[nt].w));
                }
            }
        }
        __syncthreads();
    }

    // Fused LSTM epilogue. Warp col block = one b8 (8 units x 4 gates);
    // gate g = nt; unit u = 2*tig + c; j = b8*8 + u.
    const int b8 = (tile & 15) * 4 + wc;
    float* hn = (float*)g_hf4[cur ^ 1];
    const int jb = b8 * 8 + 2 * tig;
    const float2 bi = *(const float2*)&g_bc[jb];
    const float2 bfv = *(const float2*)&g_bc[512 + jb];
    const float2 bg = *(const float2*)&g_bc[1024 + jb];
    const float2 bo = *(const float2*)&g_bc[1536 + jb];
#pragma unroll
    for (int mt = 0; mt < 4; mt++) {
#pragma unroll
        for (int rh = 0; rh < 2; rh++) {
            const int m = (tile >> 4) * 128 + wr * 64 + mt * 16 + rh * 8 + gid;
            float2 cv = *(const float2*)&g_c[(size_t)m * HID + jb];
            float hh[2];
#pragma unroll
            for (int c = 0; c < 2; c++) {
                const int r = rh * 2 + c;
                float gi = acc[mt][0][r] + (c ? bi.y : bi.x);
                float gf = acc[mt][1][r] + (c ? bfv.y : bfv.x);
                float gg = acc[mt][2][r] + (c ? bg.y : bg.x);
                float go = acc[mt][3][r] + (c ? bo.y : bo.x);
                float cn = fast_sig(gf) * (c ? cv.y : cv.x)
                         + fast_sig(gi) * fast_tanh(gg);
                if (c) cv.y = cn; else cv.x = cn;
                hh[c] = tfr(fast_sig(go) * fast_tanh(cn));
            }
            *(float2*)&g_c[(size_t)m * HID + jb] = cv;
#pragma unroll
            for (int c = 0; c < 2; c++) {
                int j = jb + c;
                int kc = j >> 4, rem = j & 15, s = rem >> 2, tg2 = rem & 3;
                hn[(((kc * 128 + (m >> 3)) * 32 + gid * 4 + tg2) << 2) + s] = hh[c];
            }
        }
    }
}

// ---------------------------------------------------------------------------
// MLP inner GEMM: A frag-major in smem (8 rows), W frag-major via LDG.
// ---------------------------------------------------------------------------
template <int KC, int NN>
__device__ __forceinline__ void mlp_compute(const float* __restrict__ sA,
                                            const float4* __restrict__ Wf,
                                            int n8b, int lane, float (&acc)[NN][4]) {
#pragma unroll
    for (int ni = 0; ni < NN; ni++)
#pragma unroll
        for (int r = 0; r < 4; r++) acc[ni][r] = 0.f;
#pragma unroll
    for (int kc = 0; kc < KC; kc++) {
        float4 av = *(const float4*)&sA[(kc * 32 + lane) * 4];
        uint32_t a0 = __float_as_uint(av.x), a2 = __float_as_uint(av.y);
        uint32_t e0 = __float_as_uint(av.z), e2 = __float_as_uint(av.w);
#pragma unroll
        for (int ni = 0; ni < NN; ni++) {
            float4 bv = Wf[(size_t)(n8b + ni) * KC * 32 + kc * 32 + lane];
            mma_tf32(acc[ni][0], acc[ni][1], acc[ni][2], acc[ni][3],
                     a0, 0u, a2, 0u, __float_as_uint(bv.x), __float_as_uint(bv.y));
            mma_tf32(acc[ni][0], acc[ni][1], acc[ni][2], acc[ni][3],
                     e0, 0u, e2, 0u, __float_as_uint(bv.z), __float_as_uint(bv.w));
        }
    }
}

__device__ __forceinline__ void store_zfrag(float* sZ, int gid, int j, float v) {
    int kc = j >> 4, rem = j & 15, s = rem >> 2, tg2 = rem & 3;
    sZ[((kc * 32 + gid * 4 + tg2) << 2) + s] = v;
}

// ---------------------------------------------------------------------------
// Fused 3-layer MLP: CTA bid owns batch rows bid*8..bid*8+7 end-to-end.
// ---------------------------------------------------------------------------
__device__ void mlp_phase(int t, const float4* __restrict__ hf,
                          const float* __restrict__ b1,
                          const float* __restrict__ b2,
                          const float* __restrict__ b3,
                          float* __restrict__ out, float* dsm) {
    const int bid = blockIdx.x;
    const int tid = threadIdx.x, lane = tid & 31, w = tid >> 5;
    const int gid = lane >> 2, tig = lane & 3;
    float* sH = dsm + 24576;       // 16KB: h frag [kc 0..31][lane][4]
    float* sZ1 = sH + 4096;        // 4KB:  z1 frag [kc 0..7][lane][4]
    float* sZ2 = sZ1 + 1024;       // 4KB

    // stage own h rows (m8 = bid) via cp.async
#pragma unroll
    for (int j = 0; j < 4; j++) {
        int u = j * 256 + tid;     // 16B unit 0..1023: kc = u>>5, lane = u&31
        unsigned dst = (unsigned)__cvta_generic_to_shared(sH + u * 4);
        const float4* src = hf + (((size_t)(u >> 5) * 128 + bid) << 5) + (u & 31);
        CP_ASYNC16(dst, src);
    }
    CP_COMMIT();
    asm volatile("cp.async.wait_group 0;\n" ::: "memory");
    __syncthreads();

    // z1 = relu(h @ W1^T + b1): warp w -> n8 {2w, 2w+1}
    {
        float acc[2][4];
        mlp_compute<32, 2>(sH, g_W1f4, 2 * w, lane, acc);
#pragma unroll
        for (int ni = 0; ni < 2; ni++) {
            int j0 = (2 * w + ni) * 8 + 2 * tig;
            float2 bb = *(const float2*)&b1[j0];
            store_zfrag(sZ1, gid, j0,     tfr(fmaxf(acc[ni][0] + bb.x, 0.f)));
            store_zfrag(sZ1, gid, j0 + 1, tfr(fmaxf(acc[ni][1] + bb.y, 0.f)));
        }
    }
    __syncthreads();

    // z2 = relu(z1 @ W2^T + b2)
    {
        float acc[2][4];
        mlp_compute<8, 2>(sZ1, g_W2f4, 2 * w, lane, acc);
#pragma unroll
        for (int ni = 0; ni < 2; ni++) {
            int j0 = (2 * w + ni) * 8 + 2 * tig;
            float2 bb = *(const float2*)&b2[j0];
            store_zfrag(sZ2, gid, j0,     tfr(fmaxf(acc[ni][0] + bb.x, 0.f)));
            store_zfrag(sZ2, gid, j0 + 1, tfr(fmaxf(acc[ni][1] + bb.y, 0.f)));
        }
    }
    __syncthreads();

    // tok = z2 @ W3^T + b3 -> out[:, t+1, :]: warp w -> n8 {4w..4w+3}
    {
        float acc[4][4];
        mlp_compute<8, 4>(sZ2, g_W3f4, 4 * w, lane, acc);
        float* orow = out + (size_t)(bid * 8 + gid) * (SEQL * EMB)
                          + (size_t)(t + 1) * EMB;
#pragma unroll
        for (int ni = 0; ni < 4; ni++) {
            int j0 = (4 * w + ni) * 8 + 2 * tig;
            float2 bb = *(const float2*)&b3[j0];
            *(float2*)&orow[j0] = make_float2(acc[ni][0] + bb.x, acc[ni][1] + bb.y);
        }
    }
}

// ---------------------------------------------------------------------------
// Persistent kernel: ONE grid sync per step.
// ---------------------------------------------------------------------------
__global__ void __launch_bounds__(NTHR, 1)
lstm_kernel(const float* __restrict__ b1, const float* __restrict__ b2,
            const float* __restrict__ b3, float* __restrict__ out) {
    extern __shared__ __align__(16) float dsm[];
    int cur = 0;
    for (int t = 0; t < STEPS; t++) {
        phase_gates(t, cur, dsm);
        grid_sync();
        mlp_phase(t, g_hf4[cur ^ 1], b1, b2, b3, out, dsm);
        cur ^= 1;
    }
}

// ---------------------------------------------------------------------------
extern "C" void kernel_launch(void* const* d_in, const int* in_sizes, int n_in,
                              void* d_out, int out_size) {
    (void)in_sizes; (void)n_in; (void)out_size;
    const float* hidden = (const float*)d_in[0];
    const float* pts    = (const float*)d_in[1];
    const float* W_ih   = (const float*)d_in[2];
    const float* W_hh   = (const float*)d_in[3];
    const float* b_ih   = (const float*)d_in[4];
    const float* b_hh   = (const float*)d_in[5];
    const float* W1     = (const float*)d_in[6];
    const float* b1     = (const float*)d_in[7];
    const float* W2     = (const float*)d_in[8];
    const float* b2     = (const float*)d_in[9];
    const float* W3     = (const float*)d_in[10];
    const float* b3     = (const float*)d_in[11];
    float* out = (float*)d_out;

    cudaFuncSetAttribute(lstm_kernel, cudaFuncAttributeMaxDynamicSharedMemorySize, DSMEM);
    init_kernel<<<4096, 256>>>(hidden, pts, W_ih, W_hh, b_ih, b_hh, W1, W2, W3, out);
    lstm_kernel<<<NBLK, NTHR, DSMEM>>>(b1, b2, b3, out);
}